// round 3
// baseline (speedup 1.0000x reference)
#include <cuda_runtime.h>
#include <cuda_fp16.h>
#include <cstdint>

#define BATCH      16
#define TSEQ       8192
#define MDIM       256
#define ROWS_TOTAL (BATCH * TSEQ)          // 131072
#define TILE_M     128
#define N_TILES    (ROWS_TOTAL / TILE_M)   // 1024
#define NCHUNK     12                      // K = 768 split-fp16, chunks of 64
#define A_ROW_BYTES 528                    // 264 halves (256 + 8 pad)
#define A_BYTES    (TILE_M * A_ROW_BYTES)  // 67584
#define B_ROW_BYTES 144                    // 72 halves (64 + 8 pad)
#define B_BYTES    (MDIM * B_ROW_BYTES)    // 36864
#define DYN_SMEM   (1024 + 2 * A_BYTES + 2 * B_BYTES)  // 209920
#define WSUM_CHUNKS 32

// ---------------- helpers ----------------
__device__ __forceinline__ uint32_t smem_u32(const void* p) {
    uint32_t a;
    asm("{ .reg .u64 t; cvta.to.shared.u64 t, %1; cvt.u32.u64 %0, t; }" : "=r"(a) : "l"(p));
    return a;
}
#define CP_ASYNC16(dst, src) \
    asm volatile("cp.async.cg.shared.global [%0], [%1], 16;" :: "r"(dst), "l"(src) : "memory")
#define CP_COMMIT() asm volatile("cp.async.commit_group;" ::: "memory")
#define CP_WAIT1()  asm volatile("cp.async.wait_group 1;" ::: "memory")
#define CP_WAIT0()  asm volatile("cp.async.wait_group 0;" ::: "memory")

__device__ __forceinline__ uint32_t lds_u32(uint32_t a) {
    uint32_t v;
    asm volatile("ld.shared.u32 %0, [%1];" : "=r"(v) : "r"(a));
    return v;
}
__device__ __forceinline__ void sts_u64(uint32_t a, uint32_t v0, uint32_t v1) {
    asm volatile("st.shared.v2.u32 [%0], {%1, %2};" :: "r"(a), "r"(v0), "r"(v1) : "memory");
}
__device__ __forceinline__ void mma16816(float* c, const uint32_t* a, uint32_t b0, uint32_t b1) {
    asm volatile(
        "mma.sync.aligned.m16n8k16.row.col.f32.f16.f16.f32 "
        "{%0,%1,%2,%3}, {%4,%5,%6,%7}, {%8,%9}, {%0,%1,%2,%3};"
        : "+f"(c[0]), "+f"(c[1]), "+f"(c[2]), "+f"(c[3])
        : "r"(a[0]), "r"(a[1]), "r"(a[2]), "r"(a[3]), "r"(b0), "r"(b1));
}
__device__ __forceinline__ float ap_tanh(float z) {
    z = fminf(fmaxf(z, -20.f), 20.f);
    float e = __expf(2.f * z);
    return 1.f - __fdividef(2.f, e + 1.f);
}

// ---------------- global scratch ----------------
__device__ float  ap_cbias[MDIM];             // vm @ W2
__device__ __half ap_Wt16[MDIM * 512];        // [n][k]: k 0..255 = hi(W1^T), 256..511 = lo
__device__ float  ap_scores[ROWS_TOTAL];      // scores -> softmax weights (in place)
__device__ float  ap_partials[BATCH * WSUM_CHUNKS * MDIM];

// ---------------- kernel 1: prep ----------------
__global__ void ap_prep_kernel(const float* __restrict__ W1,
                               const float* __restrict__ W2,
                               const float* __restrict__ vm) {
    int n = threadIdx.x;
    if (blockIdx.x == MDIM) {
        __shared__ float vs[MDIM];
        vs[n] = vm[n];
        __syncthreads();
        float acc = 0.f;
        #pragma unroll 8
        for (int k = 0; k < MDIM; k++) acc += vs[k] * W2[k * MDIM + n];
        ap_cbias[n] = acc;
    } else {
        int k = blockIdx.x;
        float w = W1[k * MDIM + n];                 // W1[k][n] -> Wt[n][k]
        __half hi = __float2half_rn(w);
        __half lo = __float2half_rn(w - __half2float(hi));
        ap_Wt16[n * 512 + k]       = hi;
        ap_Wt16[n * 512 + 256 + k] = lo;
    }
}

// ---------------- kernel 2: scores (HMMA GEMM + fused tanh-dot) ----------------
__global__ void __launch_bounds__(256, 1)
ap_scores_kernel(const float* __restrict__ x, const float* __restrict__ vm) {
    extern __shared__ char dsm[];
    __shared__ float2 cbvm[MDIM];
    __shared__ float  sred[4][TILE_M];

    const int tid  = threadIdx.x;
    const int wid  = tid >> 5;
    const int lane = tid & 31;
    const int g    = lane >> 2;       // groupID
    const int tig  = lane & 3;        // thread-in-group
    const int m0   = (wid >> 2) * 64; // warp tile origin
    const int n0   = (wid & 3) * 64;

    uint32_t raw  = smem_u32(dsm);
    uint32_t base = (raw + 1023u) & ~1023u;
    const uint32_t aAhi = base;                     // 128 x 264 halves (hi)
    const uint32_t aAlo = base + A_BYTES;           // (lo)
    const uint32_t aB   = base + 2 * A_BYTES;       // 2 x (256 x 72 halves)

    cbvm[tid] = make_float2(ap_cbias[tid], vm[tid]);

    // ---- load x tile (128 x 256 fp32), split to fp16 hi/lo in smem ----
    const float* xt = x + (size_t)blockIdx.x * TILE_M * MDIM;
    #pragma unroll 4
    for (int it = 0; it < 32; it++) {
        int id   = it * 256 + tid;        // 0..8191 float4s
        int row  = id >> 6;
        int col0 = (id & 63) * 4;
        float4 v = *(const float4*)(xt + row * MDIM + col0);
        __half2 h0 = __floats2half2_rn(v.x, v.y);
        __half2 h1 = __floats2half2_rn(v.z, v.w);
        __half2 l0 = __floats2half2_rn(v.x - __low2float(h0), v.y - __high2float(h0));
        __half2 l1 = __floats2half2_rn(v.z - __low2float(h1), v.w - __high2float(h1));
        uint32_t off = row * A_ROW_BYTES + col0 * 2;
        sts_u64(aAhi + off, *(uint32_t*)&h0, *(uint32_t*)&h1);
        sts_u64(aAlo + off, *(uint32_t*)&l0, *(uint32_t*)&l1);
    }

    // ---- B prefetch machinery (cp.async, double buffer) ----
    const __half* wt = ap_Wt16;
    auto prefetch = [&](int c) {
        int buf  = c & 1;
        int koff = (c < 8) ? ((c & 3) * 64) : (256 + (c & 3) * 64);
        uint32_t dstb = aB + buf * B_BYTES;
        #pragma unroll
        for (int it = 0; it < 8; it++) {
            int idx = it * 256 + tid;     // 0..2047
            int n = idx >> 3, j = idx & 7;
            CP_ASYNC16(dstb + n * B_ROW_BYTES + j * 16,
                       (const void*)(wt + n * 512 + koff + j * 8));
        }
    };
    prefetch(0);
    CP_COMMIT();

    // precomputed fragment row offsets
    uint32_t arow[4], brow[8];
    #pragma unroll
    for (int mi = 0; mi < 4; mi++) arow[mi] = (m0 + mi * 16 + g) * A_ROW_BYTES + tig * 4;
    #pragma unroll
    for (int ni = 0; ni < 8; ni++) brow[ni] = (n0 + ni * 8 + g) * B_ROW_BYTES + tig * 4;

    float acc[4][8][4];
    #pragma unroll
    for (int mi = 0; mi < 4; mi++)
        #pragma unroll
        for (int ni = 0; ni < 8; ni++)
            #pragma unroll
            for (int j = 0; j < 4; j++) acc[mi][ni][j] = 0.f;

    // ---- main loop: 12 K=64 chunks (xh.Wh 0-3, xl.Wh 4-7, xh.Wl 8-11) ----
    for (int c = 0; c < NCHUNK; c++) {
        if (c < NCHUNK - 1) { prefetch(c + 1); CP_COMMIT(); CP_WAIT1(); }
        else                { CP_WAIT0(); }
        __syncthreads();
        uint32_t abase = ((c >= 4 && c < 8) ? aAlo : aAhi) + (c & 3) * 128;  // koff*2B
        uint32_t bbase = aB + (c & 1) * B_BYTES;
        #pragma unroll
        for (int kk = 0; kk < 4; kk++) {
            uint32_t a[4][4];
            #pragma unroll
            for (int mi = 0; mi < 4; mi++) {
                uint32_t ad = abase + arow[mi] + kk * 32;
                a[mi][0] = lds_u32(ad);
                a[mi][1] = lds_u32(ad + 8 * A_ROW_BYTES);
                a[mi][2] = lds_u32(ad + 16);
                a[mi][3] = lds_u32(ad + 8 * A_ROW_BYTES + 16);
            }
            #pragma unroll
            for (int ni = 0; ni < 8; ni++) {
                uint32_t bd = bbase + brow[ni] + kk * 32;
                uint32_t b0 = lds_u32(bd);
                uint32_t b1 = lds_u32(bd + 16);
                #pragma unroll
                for (int mi = 0; mi < 4; mi++) mma16816(acc[mi][ni], a[mi], b0, b1);
            }
        }
        __syncthreads();
    }

    // ---- epilogue: score[r] = sum_col tanh(D + cb[col]) * vm[col] ----
    float rs[4][2];
    #pragma unroll
    for (int mi = 0; mi < 4; mi++) { rs[mi][0] = 0.f; rs[mi][1] = 0.f; }
    #pragma unroll
    for (int mi = 0; mi < 4; mi++)
        #pragma unroll
        for (int ni = 0; ni < 8; ni++)
            #pragma unroll
            for (int j = 0; j < 4; j++) {
                int col = n0 + ni * 8 + tig * 2 + (j & 1);
                float2 cv = cbvm[col];
                rs[mi][j >> 1] += ap_tanh(acc[mi][ni][j] + cv.x) * cv.y;
            }
    #pragma unroll
    for (int mi = 0; mi < 4; mi++)
        #pragma unroll
        for (int h = 0; h < 2; h++) {
            float v = rs[mi][h];
            v += __shfl_xor_sync(0xFFFFFFFFu, v, 1);
            v += __shfl_xor_sync(0xFFFFFFFFu, v, 2);
            if (tig == 0) sred[wid & 3][m0 + mi * 16 + h * 8 + g] = v;
        }
    __syncthreads();
    if (tid < TILE_M) {
        float s = sred[0][tid] + sred[1][tid] + sred[2][tid] + sred[3][tid];
        ap_scores[(size_t)blockIdx.x * TILE_M + tid] = s;
    }
}

// ---------------- kernel 3: softmax over T ----------------
__global__ void __launch_bounds__(1024) ap_softmax_kernel() {
    __shared__ float red[32];
    const int b = blockIdx.x, tid = threadIdx.x;
    float* sc = ap_scores + b * TSEQ;
    float v[8];
    float m = -1e30f;
    #pragma unroll
    for (int i = 0; i < 8; i++) { v[i] = sc[tid + i * 1024]; m = fmaxf(m, v[i]); }
    #pragma unroll
    for (int o = 16; o > 0; o >>= 1) m = fmaxf(m, __shfl_xor_sync(0xFFFFFFFFu, m, o));
    if ((tid & 31) == 0) red[tid >> 5] = m;
    __syncthreads();
    if (tid < 32) {
        m = red[tid];
        #pragma unroll
        for (int o = 16; o > 0; o >>= 1) m = fmaxf(m, __shfl_xor_sync(0xFFFFFFFFu, m, o));
        red[tid] = m;
    }
    __syncthreads();
    m = red[0];
    float s = 0.f;
    #pragma unroll
    for (int i = 0; i < 8; i++) { v[i] = __expf(v[i] - m); s += v[i]; }
    #pragma unroll
    for (int o = 16; o > 0; o >>= 1) s += __shfl_xor_sync(0xFFFFFFFFu, s, o);
    __syncthreads();
    if ((tid & 31) == 0) red[tid >> 5] = s;
    __syncthreads();
    if (tid < 32) {
        s = red[tid];
        #pragma unroll
        for (int o = 16; o > 0; o >>= 1) s += __shfl_xor_sync(0xFFFFFFFFu, s, o);
        red[tid] = s;
    }
    __syncthreads();
    float inv = __fdividef(1.f, red[0]);
    #pragma unroll
    for (int i = 0; i < 8; i++) sc[tid + i * 1024] = v[i] * inv;
}

// ---------------- kernel 4: weighted sum partials ----------------
__global__ void __launch_bounds__(256) ap_wsum_kernel(const float* __restrict__ x) {
    __shared__ float ws[256];
    const int chunk = blockIdx.x, b = blockIdx.y, tid = threadIdx.x;
    const int t0 = chunk * 256;
    ws[tid] = ap_scores[b * TSEQ + t0 + tid];
    __syncthreads();
    const float* xb = x + ((size_t)b * TSEQ + t0) * MDIM;
    float acc = 0.f;
    #pragma unroll 4
    for (int t = 0; t < 256; t++) acc += ws[t] * xb[(size_t)t * MDIM + tid];
    ap_partials[(b * WSUM_CHUNKS + chunk) * MDIM + tid] = acc;
}

// ---------------- kernel 5: final reduce ----------------
__global__ void __launch_bounds__(256) ap_final_kernel(float* __restrict__ out) {
    const int b = blockIdx.x, tid = threadIdx.x;
    float acc = 0.f;
    #pragma unroll
    for (int c = 0; c < WSUM_CHUNKS; c++)
        acc += ap_partials[(b * WSUM_CHUNKS + c) * MDIM + tid];
    out[b * MDIM + tid] = acc;
}

// ---------------- launch ----------------
extern "C" void kernel_launch(void* const* d_in, const int* in_sizes, int n_in,
                              void* d_out, int out_size) {
    const float* x  = (const float*)d_in[0];
    const float* W1 = (const float*)d_in[1];
    const float* W2 = (const float*)d_in[2];
    const float* vm = (const float*)d_in[3];
    float* out = (float*)d_out;

    cudaFuncSetAttribute(ap_scores_kernel, cudaFuncAttributeMaxDynamicSharedMemorySize, DYN_SMEM);

    ap_prep_kernel<<<MDIM + 1, 256>>>(W1, W2, vm);
    ap_scores_kernel<<<N_TILES, 256, DYN_SMEM>>>(x, vm);
    ap_softmax_kernel<<<BATCH, 1024>>>();
    ap_wsum_kernel<<<dim3(WSUM_CHUNKS, BATCH), 256>>>(x);
    ap_final_kernel<<<BATCH, 256>>>(out);
}

// round 4
// speedup vs baseline: 1.3446x; 1.3446x over previous
#include <cuda_runtime.h>
#include <cuda_fp16.h>
#include <cstdint>

#define BATCH      16
#define TSEQ       8192
#define MDIM       256
#define ROWS_TOTAL (BATCH * TSEQ)          // 131072
#define TILE_M     64
#define N_TILES    (ROWS_TOTAL / TILE_M)   // 2048
#define A_ROW_BYTES 528                    // 264 halves (256 + 8 pad)
#define A_BYTES    (TILE_M * A_ROW_BYTES)  // 33792
#define B_ROW_BYTES 144                    // 72 halves (64 + 8 pad)
#define B_BYTES    (MDIM * B_ROW_BYTES)    // 36864
#define DYN_SMEM   (1024 + 2 * A_BYTES + B_BYTES)   // 105472
#define WSUM_CHUNKS 64
#define WSUM_ROWS   (TSEQ / WSUM_CHUNKS)   // 128

// ---------------- helpers ----------------
__device__ __forceinline__ uint32_t smem_u32(const void* p) {
    uint32_t a;
    asm("{ .reg .u64 t; cvta.to.shared.u64 t, %1; cvt.u32.u64 %0, t; }" : "=r"(a) : "l"(p));
    return a;
}
#define CP_ASYNC16(dst, src) \
    asm volatile("cp.async.cg.shared.global [%0], [%1], 16;" :: "r"(dst), "l"(src) : "memory")
#define CP_COMMIT() asm volatile("cp.async.commit_group;" ::: "memory")
#define CP_WAIT0()  asm volatile("cp.async.wait_group 0;" ::: "memory")

__device__ __forceinline__ uint32_t lds_u32(uint32_t a) {
    uint32_t v;
    asm volatile("ld.shared.u32 %0, [%1];" : "=r"(v) : "r"(a));
    return v;
}
__device__ __forceinline__ void sts_u64(uint32_t a, uint32_t v0, uint32_t v1) {
    asm volatile("st.shared.v2.u32 [%0], {%1, %2};" :: "r"(a), "r"(v0), "r"(v1) : "memory");
}
__device__ __forceinline__ void mma16816(float* c, const uint32_t* a, uint32_t b0, uint32_t b1) {
    asm volatile(
        "mma.sync.aligned.m16n8k16.row.col.f32.f16.f16.f32 "
        "{%0,%1,%2,%3}, {%4,%5,%6,%7}, {%8,%9}, {%0,%1,%2,%3};"
        : "+f"(c[0]), "+f"(c[1]), "+f"(c[2]), "+f"(c[3])
        : "r"(a[0]), "r"(a[1]), "r"(a[2]), "r"(a[3]), "r"(b0), "r"(b1));
}
__device__ __forceinline__ float ap_tanh(float z) {
    z = fminf(fmaxf(z, -20.f), 20.f);
    float e = __expf(2.f * z);
    return 1.f - __fdividef(2.f, e + 1.f);
}

// ---------------- global scratch ----------------
__device__ float  ap_cbias[MDIM];             // vm @ W2
__device__ __half ap_Wt16[MDIM * 512];        // [n][k]: k 0..255 = hi(W1^T) (lo unused now)
__device__ float  ap_scores[ROWS_TOTAL];      // scores -> softmax weights (in place)
__device__ float  ap_partials[BATCH * WSUM_CHUNKS * MDIM];

// ---------------- kernel 1: prep ----------------
__global__ void ap_prep_kernel(const float* __restrict__ W1,
                               const float* __restrict__ W2,
                               const float* __restrict__ vm) {
    int n = threadIdx.x;
    if (blockIdx.x == MDIM) {
        __shared__ float vs[MDIM];
        vs[n] = vm[n];
        __syncthreads();
        float acc = 0.f;
        #pragma unroll 8
        for (int k = 0; k < MDIM; k++) acc += vs[k] * W2[k * MDIM + n];
        ap_cbias[n] = acc;
    } else {
        int k = blockIdx.x;
        float w = W1[k * MDIM + n];               // W1[k][n] -> Wt[n][k]
        ap_Wt16[n * 512 + k] = __float2half_rn(w);
    }
}

// ---------------- kernel 2: scores (HMMA GEMM + fused tanh-dot) ----------------
__global__ void __launch_bounds__(256, 2)
ap_scores_kernel(const float* __restrict__ x, const float* __restrict__ vm) {
    extern __shared__ char dsm[];
    __shared__ float2 cbvm[MDIM];
    __shared__ float  sred[4][TILE_M];

    const int tid   = threadIdx.x;
    const int wid   = tid >> 5;
    const int lane  = tid & 31;
    const int g     = lane >> 2;        // groupID
    const int tig   = lane & 3;         // thread-in-group
    const int mhalf = wid >> 2;         // 0/1 -> rows 0-31 / 32-63
    const int nquad = wid & 3;          // 0..3 -> cols q*64..
    const int m0    = mhalf * 32;
    const int n0    = nquad * 64;

    uint32_t raw  = smem_u32(dsm);
    uint32_t base = (raw + 1023u) & ~1023u;
    const uint32_t aAhi = base;                 // 64 x 264 halves (hi)
    const uint32_t aAlo = base + A_BYTES;       // (lo)
    const uint32_t aB   = base + 2 * A_BYTES;   // 256 x 72 halves (single buffer)

    cbvm[tid] = make_float2(ap_cbias[tid], vm[tid]);

    // ---- load x tile (64 x 256 fp32), split to fp16 hi/lo in smem ----
    const float* xt = x + (size_t)blockIdx.x * TILE_M * MDIM;
    #pragma unroll 4
    for (int it = 0; it < 16; it++) {
        int id   = it * 256 + tid;      // 0..4095 float4s
        int row  = id >> 6;
        int col0 = (id & 63) * 4;
        float4 v = *(const float4*)(xt + row * MDIM + col0);
        __half2 h0 = __floats2half2_rn(v.x, v.y);
        __half2 h1 = __floats2half2_rn(v.z, v.w);
        __half2 l0 = __floats2half2_rn(v.x - __low2float(h0), v.y - __high2float(h0));
        __half2 l1 = __floats2half2_rn(v.z - __low2float(h1), v.w - __high2float(h1));
        uint32_t off = row * A_ROW_BYTES + col0 * 2;
        sts_u64(aAhi + off, *(uint32_t*)&h0, *(uint32_t*)&h1);
        sts_u64(aAlo + off, *(uint32_t*)&l0, *(uint32_t*)&l1);
    }

    // fragment row offsets
    uint32_t arow[2], brow[8];
    #pragma unroll
    for (int mi = 0; mi < 2; mi++) arow[mi] = (m0 + mi * 16 + g) * A_ROW_BYTES + tig * 4;
    #pragma unroll
    for (int ni = 0; ni < 8; ni++) brow[ni] = (n0 + ni * 8 + g) * B_ROW_BYTES + tig * 4;

    float acc[2][8][4];
    #pragma unroll
    for (int mi = 0; mi < 2; mi++)
        #pragma unroll
        for (int ni = 0; ni < 8; ni++)
            #pragma unroll
            for (int j = 0; j < 4; j++) acc[mi][ni][j] = 0.f;

    const __half* wt = ap_Wt16;

    // ---- main loop: 4 B chunks (k64 of W_hi), each used for A_hi and A_lo ----
    for (int j = 0; j < 4; j++) {
        __syncthreads();                           // prior MMAs done using B buffer
        #pragma unroll
        for (int it = 0; it < 8; it++) {
            int idx = it * 256 + tid;              // 0..2047
            int n = idx >> 3, jj = idx & 7;
            CP_ASYNC16(aB + n * B_ROW_BYTES + jj * 16,
                       (const void*)(wt + n * 512 + j * 64 + jj * 8));
        }
        CP_COMMIT();
        CP_WAIT0();
        __syncthreads();                           // B chunk j visible to all

        #pragma unroll
        for (int pass = 0; pass < 2; pass++) {
            uint32_t abase = (pass ? aAlo : aAhi) + j * 128;
            #pragma unroll
            for (int kk = 0; kk < 4; kk++) {
                uint32_t a[2][4];
                #pragma unroll
                for (int mi = 0; mi < 2; mi++) {
                    uint32_t ad = abase + arow[mi] + kk * 32;
                    a[mi][0] = lds_u32(ad);
                    a[mi][1] = lds_u32(ad + 8 * A_ROW_BYTES);
                    a[mi][2] = lds_u32(ad + 16);
                    a[mi][3] = lds_u32(ad + 8 * A_ROW_BYTES + 16);
                }
                #pragma unroll
                for (int ni = 0; ni < 8; ni++) {
                    uint32_t bd = aB + brow[ni] + kk * 32;
                    uint32_t b0 = lds_u32(bd);
                    uint32_t b1 = lds_u32(bd + 16);
                    #pragma unroll
                    for (int mi = 0; mi < 2; mi++) mma16816(acc[mi][ni], a[mi], b0, b1);
                }
            }
        }
    }

    // ---- epilogue: score[r] = sum_col tanh(D + cb[col]) * vm[col] ----
    float rs[2][2];
    #pragma unroll
    for (int mi = 0; mi < 2; mi++) { rs[mi][0] = 0.f; rs[mi][1] = 0.f; }
    #pragma unroll
    for (int mi = 0; mi < 2; mi++)
        #pragma unroll
        for (int ni = 0; ni < 8; ni++)
            #pragma unroll
            for (int j = 0; j < 4; j++) {
                int col = n0 + ni * 8 + tig * 2 + (j & 1);
                float2 cv = cbvm[col];
                rs[mi][j >> 1] += ap_tanh(acc[mi][ni][j] + cv.x) * cv.y;
            }
    #pragma unroll
    for (int mi = 0; mi < 2; mi++)
        #pragma unroll
        for (int h = 0; h < 2; h++) {
            float v = rs[mi][h];
            v += __shfl_xor_sync(0xFFFFFFFFu, v, 1);
            v += __shfl_xor_sync(0xFFFFFFFFu, v, 2);
            if (tig == 0) sred[nquad][m0 + mi * 16 + h * 8 + g] = v;
        }
    __syncthreads();
    if (tid < TILE_M) {
        float s = sred[0][tid] + sred[1][tid] + sred[2][tid] + sred[3][tid];
        ap_scores[(size_t)blockIdx.x * TILE_M + tid] = s;
    }
}

// ---------------- kernel 3: softmax over T ----------------
__global__ void __launch_bounds__(1024) ap_softmax_kernel() {
    __shared__ float red[32];
    const int b = blockIdx.x, tid = threadIdx.x;
    float* sc = ap_scores + b * TSEQ;
    float v[8];
    float m = -1e30f;
    #pragma unroll
    for (int i = 0; i < 8; i++) { v[i] = sc[tid + i * 1024]; m = fmaxf(m, v[i]); }
    #pragma unroll
    for (int o = 16; o > 0; o >>= 1) m = fmaxf(m, __shfl_xor_sync(0xFFFFFFFFu, m, o));
    if ((tid & 31) == 0) red[tid >> 5] = m;
    __syncthreads();
    if (tid < 32) {
        m = red[tid];
        #pragma unroll
        for (int o = 16; o > 0; o >>= 1) m = fmaxf(m, __shfl_xor_sync(0xFFFFFFFFu, m, o));
        red[tid] = m;
    }
    __syncthreads();
    m = red[0];
    float s = 0.f;
    #pragma unroll
    for (int i = 0; i < 8; i++) { v[i] = __expf(v[i] - m); s += v[i]; }
    #pragma unroll
    for (int o = 16; o > 0; o >>= 1) s += __shfl_xor_sync(0xFFFFFFFFu, s, o);
    __syncthreads();
    if ((tid & 31) == 0) red[tid >> 5] = s;
    __syncthreads();
    if (tid < 32) {
        s = red[tid];
        #pragma unroll
        for (int o = 16; o > 0; o >>= 1) s += __shfl_xor_sync(0xFFFFFFFFu, s, o);
        red[tid] = s;
    }
    __syncthreads();
    float inv = __fdividef(1.f, red[0]);
    #pragma unroll
    for (int i = 0; i < 8; i++) sc[tid + i * 1024] = v[i] * inv;
}

// ---------------- kernel 4: weighted sum partials ----------------
__global__ void __launch_bounds__(256) ap_wsum_kernel(const float* __restrict__ x) {
    __shared__ float ws[WSUM_ROWS];
    const int chunk = blockIdx.x, b = blockIdx.y, tid = threadIdx.x;
    const int t0 = chunk * WSUM_ROWS;
    if (tid < WSUM_ROWS) ws[tid] = ap_scores[b * TSEQ + t0 + tid];
    __syncthreads();
    const float* xb = x + ((size_t)b * TSEQ + t0) * MDIM;
    float a0 = 0.f, a1 = 0.f;
    #pragma unroll 8
    for (int t = 0; t < WSUM_ROWS; t += 2) {
        a0 += ws[t]     * xb[(size_t)t * MDIM + tid];
        a1 += ws[t + 1] * xb[(size_t)(t + 1) * MDIM + tid];
    }
    ap_partials[(b * WSUM_CHUNKS + chunk) * MDIM + tid] = a0 + a1;
}

// ---------------- kernel 5: final reduce ----------------
__global__ void __launch_bounds__(256) ap_final_kernel(float* __restrict__ out) {
    const int b = blockIdx.x, tid = threadIdx.x;
    float acc = 0.f;
    #pragma unroll
    for (int c = 0; c < WSUM_CHUNKS; c++)
        acc += ap_partials[(b * WSUM_CHUNKS + c) * MDIM + tid];
    out[b * MDIM + tid] = acc;
}

// ---------------- launch ----------------
extern "C" void kernel_launch(void* const* d_in, const int* in_sizes, int n_in,
                              void* d_out, int out_size) {
    const float* x  = (const float*)d_in[0];
    const float* W1 = (const float*)d_in[1];
    const float* W2 = (const float*)d_in[2];
    const float* vm = (const float*)d_in[3];
    float* out = (float*)d_out;

    cudaFuncSetAttribute(ap_scores_kernel, cudaFuncAttributeMaxDynamicSharedMemorySize, DYN_SMEM);

    ap_prep_kernel<<<MDIM + 1, 256>>>(W1, W2, vm);
    ap_scores_kernel<<<N_TILES, 256, DYN_SMEM>>>(x, vm);
    ap_softmax_kernel<<<BATCH, 1024>>>();
    ap_wsum_kernel<<<dim3(WSUM_CHUNKS, BATCH), 256>>>(x);
    ap_final_kernel<<<BATCH, 256>>>(out);
}

// round 5
// speedup vs baseline: 2.0494x; 1.5242x over previous
#include <cuda_runtime.h>
#include <cuda_fp16.h>
#include <cstdint>

#define BATCH      16
#define TSEQ       8192
#define MDIM       256
#define ROWS_TOTAL (BATCH * TSEQ)          // 131072
#define TILE_M     64
#define N_TILES    (ROWS_TOTAL / TILE_M)   // 2048
#define A_ROW_BYTES 528                    // 264 halves (256 + 8 pad)
#define A_BYTES    (TILE_M * A_ROW_BYTES)  // 33792
#define B_ROW_BYTES 144                    // 72 halves (64 + 8 pad)
#define B_BYTES    (MDIM * B_ROW_BYTES)    // 36864
#define DYN_SMEM   (1024 + A_BYTES + 2 * B_BYTES)   // 108544 (x2 CTA = 217KB/SM)
#define WSUM_CHUNKS 64
#define WSUM_ROWS   (TSEQ / WSUM_CHUNKS)   // 128

// ---------------- helpers ----------------
__device__ __forceinline__ uint32_t smem_u32(const void* p) {
    uint32_t a;
    asm("{ .reg .u64 t; cvta.to.shared.u64 t, %1; cvt.u32.u64 %0, t; }" : "=r"(a) : "l"(p));
    return a;
}
#define CP_ASYNC16(dst, src) \
    asm volatile("cp.async.cg.shared.global [%0], [%1], 16;" :: "r"(dst), "l"(src) : "memory")
#define CP_COMMIT() asm volatile("cp.async.commit_group;" ::: "memory")
#define CP_WAIT1()  asm volatile("cp.async.wait_group 1;" ::: "memory")
#define CP_WAIT0()  asm volatile("cp.async.wait_group 0;" ::: "memory")

__device__ __forceinline__ uint32_t lds_u32(uint32_t a) {
    uint32_t v;
    asm volatile("ld.shared.u32 %0, [%1];" : "=r"(v) : "r"(a));
    return v;
}
__device__ __forceinline__ void sts_u64(uint32_t a, uint32_t v0, uint32_t v1) {
    asm volatile("st.shared.v2.u32 [%0], {%1, %2};" :: "r"(a), "r"(v0), "r"(v1) : "memory");
}
__device__ __forceinline__ void mma16816(float* c, const uint32_t* a, uint32_t b0, uint32_t b1) {
    asm volatile(
        "mma.sync.aligned.m16n8k16.row.col.f32.f16.f16.f32 "
        "{%0,%1,%2,%3}, {%4,%5,%6,%7}, {%8,%9}, {%0,%1,%2,%3};"
        : "+f"(c[0]), "+f"(c[1]), "+f"(c[2]), "+f"(c[3])
        : "r"(a[0]), "r"(a[1]), "r"(a[2]), "r"(a[3]), "r"(b0), "r"(b1));
}
__device__ __forceinline__ float ap_tanh(float z) {
    z = fminf(fmaxf(z, -20.f), 20.f);
    float e = __expf(2.f * z);
    return 1.f - __fdividef(2.f, e + 1.f);
}

// ---------------- global scratch ----------------
__device__ float  ap_cbias[MDIM];             // vm @ W2
__device__ __half ap_Wt16[MDIM * MDIM];       // [n][k] = fp16(W1^T)
__device__ float  ap_scores[ROWS_TOTAL];      // scores -> softmax weights (in place)
__device__ float  ap_partials[BATCH * WSUM_CHUNKS * MDIM];

// ---------------- kernel 1: prep ----------------
__global__ void ap_prep_kernel(const float* __restrict__ W1,
                               const float* __restrict__ W2,
                               const float* __restrict__ vm) {
    int n = threadIdx.x;
    if (blockIdx.x == MDIM) {
        __shared__ float vs[MDIM];
        vs[n] = vm[n];
        __syncthreads();
        float acc = 0.f;
        #pragma unroll 8
        for (int k = 0; k < MDIM; k++) acc += vs[k] * W2[k * MDIM + n];
        ap_cbias[n] = acc;
    } else {
        int k = blockIdx.x;
        ap_Wt16[n * MDIM + k] = __float2half_rn(W1[k * MDIM + n]);   // W1[k][n] -> Wt[n][k]
    }
}

// ---------------- kernel 2: scores (fp16 HMMA K=256 + fused tanh-dot) ----------------
__global__ void __launch_bounds__(256, 2)
ap_scores_kernel(const float* __restrict__ x, const float* __restrict__ vm) {
    extern __shared__ char dsm[];
    __shared__ float2 cbvm[MDIM];
    __shared__ float  sred[4][TILE_M];

    const int tid   = threadIdx.x;
    const int wid   = tid >> 5;
    const int lane  = tid & 31;
    const int g     = lane >> 2;        // groupID
    const int tig   = lane & 3;         // thread-in-group
    const int mhalf = wid >> 2;         // rows 0-31 / 32-63
    const int nquad = wid & 3;          // cols q*64..
    const int m0    = mhalf * 32;
    const int n0    = nquad * 64;

    uint32_t raw  = smem_u32(dsm);
    uint32_t base = (raw + 1023u) & ~1023u;
    const uint32_t aA = base;                   // 64 x 264 halves
    const uint32_t aB = base + A_BYTES;         // 2 x (256 x 72 halves)

    cbvm[tid] = make_float2(ap_cbias[tid], vm[tid]);

    const __half* wt = ap_Wt16;
    auto prefetch = [&](int c) {
        uint32_t dstb = aB + (c & 1) * B_BYTES;
        #pragma unroll
        for (int it = 0; it < 8; it++) {
            int idx = it * 256 + tid;              // 0..2047
            int n = idx >> 3, jj = idx & 7;
            CP_ASYNC16(dstb + n * B_ROW_BYTES + jj * 16,
                       (const void*)(wt + n * MDIM + c * 64 + jj * 8));
        }
    };
    prefetch(0);
    CP_COMMIT();

    // ---- load x tile (64 x 256 fp32) -> fp16 in smem ----
    const float* xt = x + (size_t)blockIdx.x * TILE_M * MDIM;
    #pragma unroll 4
    for (int it = 0; it < 16; it++) {
        int id   = it * 256 + tid;      // 0..4095 float4s
        int row  = id >> 6;
        int col0 = (id & 63) * 4;
        float4 v = *(const float4*)(xt + row * MDIM + col0);
        __half2 h0 = __floats2half2_rn(v.x, v.y);
        __half2 h1 = __floats2half2_rn(v.z, v.w);
        sts_u64(aA + row * A_ROW_BYTES + col0 * 2, *(uint32_t*)&h0, *(uint32_t*)&h1);
    }

    // fragment row offsets
    uint32_t arow[2], brow[8];
    #pragma unroll
    for (int mi = 0; mi < 2; mi++) arow[mi] = (m0 + mi * 16 + g) * A_ROW_BYTES + tig * 4;
    #pragma unroll
    for (int ni = 0; ni < 8; ni++) brow[ni] = (n0 + ni * 8 + g) * B_ROW_BYTES + tig * 4;

    float acc[2][8][4];
    #pragma unroll
    for (int mi = 0; mi < 2; mi++)
        #pragma unroll
        for (int ni = 0; ni < 8; ni++)
            #pragma unroll
            for (int j = 0; j < 4; j++) acc[mi][ni][j] = 0.f;

    // ---- main loop: 4 K=64 chunks, double-buffered B ----
    #pragma unroll
    for (int c = 0; c < 4; c++) {
        if (c < 3) { prefetch(c + 1); CP_COMMIT(); CP_WAIT1(); }
        else       { CP_WAIT0(); }
        __syncthreads();                            // B chunk c ready, A ready (c==0)
        uint32_t abase = aA + c * 128;              // +64 halves per chunk
        uint32_t bbase = aB + (c & 1) * B_BYTES;
        #pragma unroll
        for (int kk = 0; kk < 4; kk++) {
            uint32_t a[2][4];
            #pragma unroll
            for (int mi = 0; mi < 2; mi++) {
                uint32_t ad = abase + arow[mi] + kk * 32;
                a[mi][0] = lds_u32(ad);
                a[mi][1] = lds_u32(ad + 8 * A_ROW_BYTES);
                a[mi][2] = lds_u32(ad + 16);
                a[mi][3] = lds_u32(ad + 8 * A_ROW_BYTES + 16);
            }
            #pragma unroll
            for (int ni = 0; ni < 8; ni++) {
                uint32_t bd = bbase + brow[ni] + kk * 32;
                uint32_t b0 = lds_u32(bd);
                uint32_t b1 = lds_u32(bd + 16);
                #pragma unroll
                for (int mi = 0; mi < 2; mi++) mma16816(acc[mi][ni], a[mi], b0, b1);
            }
        }
        __syncthreads();                            // all reads done before buf reuse
    }

    // ---- epilogue: score[r] = sum_col tanh(D + cb[col]) * vm[col] ----
    float rs[2][2];
    #pragma unroll
    for (int mi = 0; mi < 2; mi++) { rs[mi][0] = 0.f; rs[mi][1] = 0.f; }
    #pragma unroll
    for (int mi = 0; mi < 2; mi++)
        #pragma unroll
        for (int ni = 0; ni < 8; ni++)
            #pragma unroll
            for (int j = 0; j < 4; j++) {
                int col = n0 + ni * 8 + tig * 2 + (j & 1);
                float2 cv = cbvm[col];
                rs[mi][j >> 1] += ap_tanh(acc[mi][ni][j] + cv.x) * cv.y;
            }
    #pragma unroll
    for (int mi = 0; mi < 2; mi++)
        #pragma unroll
        for (int h = 0; h < 2; h++) {
            float v = rs[mi][h];
            v += __shfl_xor_sync(0xFFFFFFFFu, v, 1);
            v += __shfl_xor_sync(0xFFFFFFFFu, v, 2);
            if (tig == 0) sred[nquad][m0 + mi * 16 + h * 8 + g] = v;
        }
    __syncthreads();
    if (tid < TILE_M) {
        float s = sred[0][tid] + sred[1][tid] + sred[2][tid] + sred[3][tid];
        ap_scores[(size_t)blockIdx.x * TILE_M + tid] = s;
    }
}

// ---------------- kernel 3: softmax over T ----------------
__global__ void __launch_bounds__(1024) ap_softmax_kernel() {
    __shared__ float red[32];
    const int b = blockIdx.x, tid = threadIdx.x;
    float* sc = ap_scores + b * TSEQ;
    float v[8];
    float m = -1e30f;
    #pragma unroll
    for (int i = 0; i < 8; i++) { v[i] = sc[tid + i * 1024]; m = fmaxf(m, v[i]); }
    #pragma unroll
    for (int o = 16; o > 0; o >>= 1) m = fmaxf(m, __shfl_xor_sync(0xFFFFFFFFu, m, o));
    if ((tid & 31) == 0) red[tid >> 5] = m;
    __syncthreads();
    if (tid < 32) {
        m = red[tid];
        #pragma unroll
        for (int o = 16; o > 0; o >>= 1) m = fmaxf(m, __shfl_xor_sync(0xFFFFFFFFu, m, o));
        red[tid] = m;
    }
    __syncthreads();
    m = red[0];
    float s = 0.f;
    #pragma unroll
    for (int i = 0; i < 8; i++) { v[i] = __expf(v[i] - m); s += v[i]; }
    #pragma unroll
    for (int o = 16; o > 0; o >>= 1) s += __shfl_xor_sync(0xFFFFFFFFu, s, o);
    __syncthreads();
    if ((tid & 31) == 0) red[tid >> 5] = s;
    __syncthreads();
    if (tid < 32) {
        s = red[tid];
        #pragma unroll
        for (int o = 16; o > 0; o >>= 1) s += __shfl_xor_sync(0xFFFFFFFFu, s, o);
        red[tid] = s;
    }
    __syncthreads();
    float inv = __fdividef(1.f, red[0]);
    #pragma unroll
    for (int i = 0; i < 8; i++) sc[tid + i * 1024] = v[i] * inv;
}

// ---------------- kernel 4: weighted sum partials (float4) ----------------
__global__ void __launch_bounds__(256) ap_wsum_kernel(const float* __restrict__ x) {
    __shared__ float  ws[WSUM_ROWS];
    __shared__ float4 sp[4][MDIM / 4];
    const int chunk = blockIdx.x, b = blockIdx.y, tid = threadIdx.x;
    const int col4 = tid & 63;          // float4 column group
    const int rg   = tid >> 6;          // row group 0..3
    const int t0 = chunk * WSUM_ROWS;
    if (tid < WSUM_ROWS) ws[tid] = ap_scores[b * TSEQ + t0 + tid];
    __syncthreads();
    const float* xb = x + ((size_t)b * TSEQ + t0) * MDIM;
    float4 a = make_float4(0.f, 0.f, 0.f, 0.f);
    #pragma unroll 8
    for (int i = 0; i < WSUM_ROWS / 4; i++) {
        int r = rg + i * 4;
        float w = ws[r];
        float4 v = *(const float4*)(xb + (size_t)r * MDIM + col4 * 4);
        a.x += w * v.x; a.y += w * v.y; a.z += w * v.z; a.w += w * v.w;
    }
    sp[rg][col4] = a;
    __syncthreads();
    if (tid < 64) {
        float4 s0 = sp[0][tid], s1 = sp[1][tid], s2 = sp[2][tid], s3 = sp[3][tid];
        float4 r = make_float4(s0.x + s1.x + s2.x + s3.x, s0.y + s1.y + s2.y + s3.y,
                               s0.z + s1.z + s2.z + s3.z, s0.w + s1.w + s2.w + s3.w);
        *(float4*)(ap_partials + (size_t)(b * WSUM_CHUNKS + chunk) * MDIM + tid * 4) = r;
    }
}

// ---------------- kernel 5: final reduce ----------------
__global__ void __launch_bounds__(256) ap_final_kernel(float* __restrict__ out) {
    const int b = blockIdx.x, tid = threadIdx.x;
    float acc = 0.f;
    #pragma unroll
    for (int c = 0; c < WSUM_CHUNKS; c++)
        acc += ap_partials[(b * WSUM_CHUNKS + c) * MDIM + tid];
    out[b * MDIM + tid] = acc;
}

// ---------------- launch ----------------
extern "C" void kernel_launch(void* const* d_in, const int* in_sizes, int n_in,
                              void* d_out, int out_size) {
    const float* x  = (const float*)d_in[0];
    const float* W1 = (const float*)d_in[1];
    const float* W2 = (const float*)d_in[2];
    const float* vm = (const float*)d_in[3];
    float* out = (float*)d_out;

    cudaFuncSetAttribute(ap_scores_kernel, cudaFuncAttributeMaxDynamicSharedMemorySize, DYN_SMEM);

    ap_prep_kernel<<<MDIM + 1, 256>>>(W1, W2, vm);
    ap_scores_kernel<<<N_TILES, 256, DYN_SMEM>>>(x, vm);
    ap_softmax_kernel<<<BATCH, 1024>>>();
    ap_wsum_kernel<<<dim3(WSUM_CHUNKS, BATCH), 256>>>(x);
    ap_final_kernel<<<BATCH, 256>>>(out);
}

// round 6
// speedup vs baseline: 2.2238x; 1.0851x over previous
#include <cuda_runtime.h>
#include <cuda_fp16.h>
#include <cstdint>

#define BATCH      16
#define TSEQ       8192
#define MDIM       256
#define ROWS_TOTAL (BATCH * TSEQ)          // 131072
#define TILE_M     64
#define N_TILES    (ROWS_TOTAL / TILE_M)   // 2048
#define A_ROW_BYTES 528                    // 264 halves (256 + 8 pad), 16B-aligned rows
#define A_BYTES    (TILE_M * A_ROW_BYTES)  // 33792
#define B_ROW_BYTES 144                    // 72 halves (64 + 8 pad)
#define B_BYTES    (MDIM * B_ROW_BYTES)    // 36864
#define DYN_SMEM   (1024 + A_BYTES + 2 * B_BYTES)   // 108544 (x2 CTA = 217KB/SM)
#define WSUM_CHUNKS 32
#define WSUM_ROWS   (TSEQ / WSUM_CHUNKS)   // 256

// ---------------- helpers ----------------
__device__ __forceinline__ uint32_t smem_u32(const void* p) {
    uint32_t a;
    asm("{ .reg .u64 t; cvta.to.shared.u64 t, %1; cvt.u32.u64 %0, t; }" : "=r"(a) : "l"(p));
    return a;
}
#define CP_ASYNC16(dst, src) \
    asm volatile("cp.async.cg.shared.global [%0], [%1], 16;" :: "r"(dst), "l"(src) : "memory")
#define CP_COMMIT() asm volatile("cp.async.commit_group;" ::: "memory")
#define CP_WAIT1()  asm volatile("cp.async.wait_group 1;" ::: "memory")
#define CP_WAIT0()  asm volatile("cp.async.wait_group 0;" ::: "memory")

__device__ __forceinline__ uint32_t lds_u32(uint32_t a) {
    uint32_t v;
    asm volatile("ld.shared.u32 %0, [%1];" : "=r"(v) : "r"(a));
    return v;
}
__device__ __forceinline__ void sts_u128(uint32_t a, uint32_t v0, uint32_t v1, uint32_t v2, uint32_t v3) {
    asm volatile("st.shared.v4.u32 [%0], {%1, %2, %3, %4};"
                 :: "r"(a), "r"(v0), "r"(v1), "r"(v2), "r"(v3) : "memory");
}
__device__ __forceinline__ void mma16816(float* c, const uint32_t* a, uint32_t b0, uint32_t b1) {
    asm volatile(
        "mma.sync.aligned.m16n8k16.row.col.f32.f16.f16.f32 "
        "{%0,%1,%2,%3}, {%4,%5,%6,%7}, {%8,%9}, {%0,%1,%2,%3};"
        : "+f"(c[0]), "+f"(c[1]), "+f"(c[2]), "+f"(c[3])
        : "r"(a[0]), "r"(a[1]), "r"(a[2]), "r"(a[3]), "r"(b0), "r"(b1));
}
__device__ __forceinline__ float tanh_fast(float x) {
    float y;
    asm("tanh.approx.f32 %0, %1;" : "=f"(y) : "f"(x));
    return y;
}

// ---------------- global scratch ----------------
__device__ float  ap_cbias[MDIM];             // vm @ W2
__device__ __half ap_Wt16[MDIM * MDIM];       // [n][k] = fp16(W1^T)
__device__ float  ap_scores[ROWS_TOTAL];      // scores -> softmax weights (in place)
__device__ float  ap_partials[BATCH * WSUM_CHUNKS * MDIM];

// ---------------- kernel 1: prep ----------------
__global__ void ap_prep_kernel(const float* __restrict__ W1,
                               const float* __restrict__ W2,
                               const float* __restrict__ vm) {
    int n = threadIdx.x;
    if (blockIdx.x == MDIM) {
        __shared__ float vs[MDIM];
        vs[n] = vm[n];
        __syncthreads();
        float acc = 0.f;
        #pragma unroll 8
        for (int k = 0; k < MDIM; k++) acc += vs[k] * W2[k * MDIM + n];
        ap_cbias[n] = acc;
    } else {
        int k = blockIdx.x;
        ap_Wt16[n * MDIM + k] = __float2half_rn(W1[k * MDIM + n]);   // W1[k][n] -> Wt[n][k]
    }
}

// ---------------- kernel 2: scores (fp16 HMMA K=256 + fused tanh-dot) ----------------
__global__ void __launch_bounds__(256, 2)
ap_scores_kernel(const float* __restrict__ x, const float* __restrict__ vm) {
    extern __shared__ char dsm[];
    __shared__ float2 cbvm[MDIM];
    __shared__ float  sred[4][TILE_M];

    const int tid   = threadIdx.x;
    const int wid   = tid >> 5;
    const int lane  = tid & 31;
    const int g     = lane >> 2;        // groupID
    const int tig   = lane & 3;         // thread-in-group
    const int mhalf = wid >> 2;         // rows 0-31 / 32-63
    const int nquad = wid & 3;          // cols q*64..
    const int m0    = mhalf * 32;
    const int n0    = nquad * 64;

    uint32_t raw  = smem_u32(dsm);
    uint32_t base = (raw + 1023u) & ~1023u;
    const uint32_t aA = base;                   // 64 x 264 halves
    const uint32_t aB = base + A_BYTES;         // 2 x (256 x 72 halves)

    cbvm[tid] = make_float2(ap_cbias[tid], vm[tid]);

    const __half* wt = ap_Wt16;
    auto prefetch = [&](int c) {
        uint32_t dstb = aB + (c & 1) * B_BYTES;
        #pragma unroll
        for (int it = 0; it < 8; it++) {
            int idx = it * 256 + tid;              // 0..2047
            int n = idx >> 3, jj = idx & 7;
            CP_ASYNC16(dstb + n * B_ROW_BYTES + jj * 16,
                       (const void*)(wt + n * MDIM + c * 64 + jj * 8));
        }
    };
    prefetch(0);
    CP_COMMIT();

    // ---- load x tile (64 x 256 fp32) -> fp16 in smem (8 floats/thread/iter) ----
    const float* xt = x + (size_t)blockIdx.x * TILE_M * MDIM;
    #pragma unroll
    for (int it = 0; it < 8; it++) {
        int id   = it * 256 + tid;      // 0..2047 groups of 8 floats
        int row  = id >> 5;
        int col0 = (id & 31) * 8;
        float4 v0 = *(const float4*)(xt + row * MDIM + col0);
        float4 v1 = *(const float4*)(xt + row * MDIM + col0 + 4);
        __half2 h0 = __floats2half2_rn(v0.x, v0.y);
        __half2 h1 = __floats2half2_rn(v0.z, v0.w);
        __half2 h2 = __floats2half2_rn(v1.x, v1.y);
        __half2 h3 = __floats2half2_rn(v1.z, v1.w);
        sts_u128(aA + row * A_ROW_BYTES + col0 * 2,
                 *(uint32_t*)&h0, *(uint32_t*)&h1, *(uint32_t*)&h2, *(uint32_t*)&h3);
    }

    // fragment row offsets
    uint32_t arow[2], brow[8];
    #pragma unroll
    for (int mi = 0; mi < 2; mi++) arow[mi] = (m0 + mi * 16 + g) * A_ROW_BYTES + tig * 4;
    #pragma unroll
    for (int ni = 0; ni < 8; ni++) brow[ni] = (n0 + ni * 8 + g) * B_ROW_BYTES + tig * 4;

    float acc[2][8][4];
    #pragma unroll
    for (int mi = 0; mi < 2; mi++)
        #pragma unroll
        for (int ni = 0; ni < 8; ni++)
            #pragma unroll
            for (int j = 0; j < 4; j++) acc[mi][ni][j] = 0.f;

    // ---- main loop: 4 K=64 chunks, double-buffered B ----
    #pragma unroll
    for (int c = 0; c < 4; c++) {
        if (c < 3) { prefetch(c + 1); CP_COMMIT(); CP_WAIT1(); }
        else       { CP_WAIT0(); }
        __syncthreads();                            // B chunk c ready, A ready (c==0)
        uint32_t abase = aA + c * 128;              // +64 halves per chunk
        uint32_t bbase = aB + (c & 1) * B_BYTES;
        #pragma unroll
        for (int kk = 0; kk < 4; kk++) {
            uint32_t a[2][4];
            #pragma unroll
            for (int mi = 0; mi < 2; mi++) {
                uint32_t ad = abase + arow[mi] + kk * 32;
                a[mi][0] = lds_u32(ad);
                a[mi][1] = lds_u32(ad + 8 * A_ROW_BYTES);
                a[mi][2] = lds_u32(ad + 16);
                a[mi][3] = lds_u32(ad + 8 * A_ROW_BYTES + 16);
            }
            #pragma unroll
            for (int ni = 0; ni < 8; ni++) {
                uint32_t bd = bbase + brow[ni] + kk * 32;
                uint32_t b0 = lds_u32(bd);
                uint32_t b1 = lds_u32(bd + 16);
                #pragma unroll
                for (int mi = 0; mi < 2; mi++) mma16816(acc[mi][ni], a[mi], b0, b1);
            }
        }
        __syncthreads();                            // all reads done before buf reuse
    }

    // ---- epilogue: score[r] = sum_col tanh(D + cb[col]) * vm[col] ----
    float rs[2][2];
    #pragma unroll
    for (int mi = 0; mi < 2; mi++) { rs[mi][0] = 0.f; rs[mi][1] = 0.f; }
    #pragma unroll
    for (int mi = 0; mi < 2; mi++)
        #pragma unroll
        for (int ni = 0; ni < 8; ni++)
            #pragma unroll
            for (int j = 0; j < 4; j++) {
                int col = n0 + ni * 8 + tig * 2 + (j & 1);
                float2 cv = cbvm[col];
                rs[mi][j >> 1] += tanh_fast(acc[mi][ni][j] + cv.x) * cv.y;
            }
    #pragma unroll
    for (int mi = 0; mi < 2; mi++)
        #pragma unroll
        for (int h = 0; h < 2; h++) {
            float v = rs[mi][h];
            v += __shfl_xor_sync(0xFFFFFFFFu, v, 1);
            v += __shfl_xor_sync(0xFFFFFFFFu, v, 2);
            if (tig == 0) sred[nquad][m0 + mi * 16 + h * 8 + g] = v;
        }
    __syncthreads();
    if (tid < TILE_M) {
        float s = sred[0][tid] + sred[1][tid] + sred[2][tid] + sred[3][tid];
        ap_scores[(size_t)blockIdx.x * TILE_M + tid] = s;
    }
}

// ---------------- kernel 3: softmax over T ----------------
__global__ void __launch_bounds__(1024) ap_softmax_kernel() {
    __shared__ float red[32];
    const int b = blockIdx.x, tid = threadIdx.x;
    float* sc = ap_scores + b * TSEQ;
    float v[8];
    float m = -1e30f;
    #pragma unroll
    for (int i = 0; i < 8; i++) { v[i] = sc[tid + i * 1024]; m = fmaxf(m, v[i]); }
    #pragma unroll
    for (int o = 16; o > 0; o >>= 1) m = fmaxf(m, __shfl_xor_sync(0xFFFFFFFFu, m, o));
    if ((tid & 31) == 0) red[tid >> 5] = m;
    __syncthreads();
    if (tid < 32) {
        m = red[tid];
        #pragma unroll
        for (int o = 16; o > 0; o >>= 1) m = fmaxf(m, __shfl_xor_sync(0xFFFFFFFFu, m, o));
        red[tid] = m;
    }
    __syncthreads();
    m = red[0];
    float s = 0.f;
    #pragma unroll
    for (int i = 0; i < 8; i++) { v[i] = __expf(v[i] - m); s += v[i]; }
    #pragma unroll
    for (int o = 16; o > 0; o >>= 1) s += __shfl_xor_sync(0xFFFFFFFFu, s, o);
    __syncthreads();
    if ((tid & 31) == 0) red[tid >> 5] = s;
    __syncthreads();
    if (tid < 32) {
        s = red[tid];
        #pragma unroll
        for (int o = 16; o > 0; o >>= 1) s += __shfl_xor_sync(0xFFFFFFFFu, s, o);
        red[tid] = s;
    }
    __syncthreads();
    float inv = __fdividef(1.f, red[0]);
    #pragma unroll
    for (int i = 0; i < 8; i++) sc[tid + i * 1024] = v[i] * inv;
}

// ---------------- kernel 4: weighted sum partials (256 rows/block, 512 thr) ----------------
__global__ void __launch_bounds__(512) ap_wsum_kernel(const float* __restrict__ x) {
    __shared__ float  ws[WSUM_ROWS];
    __shared__ float4 sp[8][MDIM / 4];
    const int chunk = blockIdx.x, b = blockIdx.y, tid = threadIdx.x;
    const int col4 = tid & 63;          // float4 column group
    const int rg   = tid >> 6;          // row group 0..7
    const int t0 = chunk * WSUM_ROWS;
    if (tid < WSUM_ROWS) ws[tid] = ap_scores[b * TSEQ + t0 + tid];
    __syncthreads();
    const float* xb = x + ((size_t)b * TSEQ + t0) * MDIM;
    float4 a = make_float4(0.f, 0.f, 0.f, 0.f);
    #pragma unroll 8
    for (int i = 0; i < WSUM_ROWS / 8; i++) {
        int r = rg + i * 8;
        float w = ws[r];
        float4 v = *(const float4*)(xb + (size_t)r * MDIM + col4 * 4);
        a.x += w * v.x; a.y += w * v.y; a.z += w * v.z; a.w += w * v.w;
    }
    sp[rg][col4] = a;
    __syncthreads();
    if (tid < 64) {
        float4 r = sp[0][tid];
        #pragma unroll
        for (int q = 1; q < 8; q++) {
            float4 s = sp[q][tid];
            r.x += s.x; r.y += s.y; r.z += s.z; r.w += s.w;
        }
        *(float4*)(ap_partials + (size_t)(b * WSUM_CHUNKS + chunk) * MDIM + tid * 4) = r;
    }
}

// ---------------- kernel 5: final reduce ----------------
__global__ void __launch_bounds__(256) ap_final_kernel(float* __restrict__ out) {
    const int b = blockIdx.x, tid = threadIdx.x;
    float acc = 0.f;
    #pragma unroll
    for (int c = 0; c < WSUM_CHUNKS; c++)
        acc += ap_partials[(b * WSUM_CHUNKS + c) * MDIM + tid];
    out[b * MDIM + tid] = acc;
}

// ---------------- launch ----------------
extern "C" void kernel_launch(void* const* d_in, const int* in_sizes, int n_in,
                              void* d_out, int out_size) {
    const float* x  = (const float*)d_in[0];
    const float* W1 = (const float*)d_in[1];
    const float* W2 = (const float*)d_in[2];
    const float* vm = (const float*)d_in[3];
    float* out = (float*)d_out;

    cudaFuncSetAttribute(ap_scores_kernel, cudaFuncAttributeMaxDynamicSharedMemorySize, DYN_SMEM);

    ap_prep_kernel<<<MDIM + 1, 256>>>(W1, W2, vm);
    ap_scores_kernel<<<N_TILES, 256, DYN_SMEM>>>(x, vm);
    ap_softmax_kernel<<<BATCH, 1024>>>();
    ap_wsum_kernel<<<dim3(WSUM_CHUNKS, BATCH), 512>>>(x);
    ap_final_kernel<<<BATCH, 256>>>(out);
}